// round 9
// baseline (speedup 1.0000x reference)
#include <cuda_runtime.h>

// EPN layer: q_out[b,i] = q[b,i] + sum_j (mlp(x_i,x_j,e_ij) - mlp(x_j,x_i,e_ij)) * mask[b,i,j]
// Decomposition: layer1 pre_ij = S_i + T_j + (e_ij @ W1c) + b1, where S=x@W1[0:65], T=x@W1[65:130].
// Both directions packed into f32x2 lanes ({ij, ji}); layer2 uses duplicated-W2 pairs from smem.

#define NB 32
#define NN 96
#define NNODE (NB*NN)

typedef unsigned long long u64;

__device__ float2 g_G[NB * 32 * NN];   // [b][k][n] = {T[b,n,k], S[b,n,k]}  (k-major for coalesced edge loads)

__device__ __forceinline__ u64 pack2(float lo, float hi) {
    u64 r; asm("mov.b64 %0, {%1, %2};" : "=l"(r) : "f"(lo), "f"(hi)); return r;
}
__device__ __forceinline__ void unpack2(u64 v, float& lo, float& hi) {
    asm("mov.b64 {%0, %1}, %2;" : "=f"(lo), "=f"(hi) : "l"(v));
}
__device__ __forceinline__ u64 fma2(u64 a, u64 b, u64 c) {
    u64 d; asm("fma.rn.f32x2 %0, %1, %2, %3;" : "=l"(d) : "l"(a), "l"(b), "l"(c)); return d;
}

// ---------------- precompute S/T per node ----------------
__global__ void epn_prep_kernel(const float* __restrict__ h,
                                const float* __restrict__ q,
                                const float* __restrict__ W1) {
    int node = blockIdx.x;               // 0..3071
    __shared__ float x[65];
    int t = threadIdx.x;                 // block = 64
    if (t < 64) x[t] = h[node * 64 + t];
    if (t == 0) x[64] = q[node];
    __syncthreads();
    if (t < 32) {
        float s = 0.f, tt = 0.f;
        #pragma unroll
        for (int d = 0; d < 65; d++) {
            float xv = x[d];
            s  = fmaf(xv, W1[d * 32 + t], s);          // W1a column t
            tt = fmaf(xv, W1[(65 + d) * 32 + t], tt);  // W1b column t
        }
        int b = node / NN, n = node % NN;
        g_G[(b * 32 + t) * NN + n] = make_float2(tt, s);
    }
}

// ---------------- main edge kernel: one block per (b,i), one thread per j ----------------
__global__ void __launch_bounds__(96, 4)
epn_main_kernel(const float* __restrict__ e,
                const float* __restrict__ q,
                const float* __restrict__ mask,
                const float* __restrict__ W1,
                const float* __restrict__ b1,
                const float* __restrict__ W2,
                const float* __restrict__ b2,
                const float* __restrict__ W3,
                float* __restrict__ out) {
    int bi = blockIdx.x;            // 0..3071 : (b,i)
    int b  = bi / NN;
    int i  = bi % NN;
    int t  = threadIdx.x;           // j = t, 0..95

    __shared__ u64   w2d[32][32];   // duplicated W2[ki][ko] pairs (8KB)
    __shared__ u64   w1c2[16][16];  // {W1c[d][2p], W1c[d][2p+1]} pairs (2KB)
    __shared__ float u_sh[32];      // S_i[k] + b1[k]
    __shared__ float v_sh[32];      // T_i[k] + b1[k]
    __shared__ float w3_sh[32];
    __shared__ u64   b2d[32];       // {b2[ko], b2[ko]}
    __shared__ float red[3];

    // ---- stage weights ----
    for (int idx = t; idx < 1024; idx += 96) {
        float w = W2[idx];
        w2d[idx >> 5][idx & 31] = pack2(w, w);
    }
    for (int idx = t; idx < 256; idx += 96) {
        int d = idx >> 4, p = idx & 15;
        float2 w = ((const float2*)(W1 + (130 + d) * 32))[p];
        w1c2[d][p] = pack2(w.x, w.y);
    }
    if (t < 32) {
        float2 g = g_G[(b * 32 + t) * NN + i];
        float bb = b1[t];
        u_sh[t]  = g.y + bb;        // S_i + b1
        v_sh[t]  = g.x + bb;        // T_i + b1
        w3_sh[t] = W3[t];
        float bv = b2[t];
        b2d[t]   = pack2(bv, bv);
    }
    __syncthreads();

    // ---- per-edge e row (16 floats) ----
    const float4* ev4 = (const float4*)(e + ((size_t)bi * NN + t) * 16);
    float4 e0 = ev4[0], e1 = ev4[1], e2 = ev4[2], e3 = ev4[3];
    float ed[16] = { e0.x, e0.y, e0.z, e0.w, e1.x, e1.y, e1.z, e1.w,
                     e2.x, e2.y, e2.z, e2.w, e3.x, e3.y, e3.z, e3.w };

    // ---- c = e @ W1c, packed over k-pairs: c2[p] = {c[2p], c[2p+1]} ----
    u64 c2[16];
    #pragma unroll
    for (int p = 0; p < 16; p++) c2[p] = 0ull;
    #pragma unroll
    for (int d = 0; d < 16; d++) {
        u64 edup = pack2(ed[d], ed[d]);
        #pragma unroll
        for (int p = 0; p < 16; p++)
            c2[p] = fma2(edup, w1c2[d][p], c2[p]);
    }

    // ---- layer1 activations packed over directions: zp[k] = {z_ij[k], z_ji[k]} ----
    const float2* Gb = g_G + (size_t)b * 32 * NN;
    u64 zp[32];
    #pragma unroll
    for (int p = 0; p < 16; p++) {
        float ca, cb;
        unpack2(c2[p], ca, cb);
        {
            int k = 2 * p;
            float2 g = Gb[k * NN + t];                  // {T_j[k], S_j[k]} coalesced
            float zl = fmaxf(ca + u_sh[k] + g.x, 0.f);  // ij: c + (S_i+b1) + T_j
            float zh = fmaxf(ca + v_sh[k] + g.y, 0.f);  // ji: c + (T_i+b1) + S_j
            zp[k] = pack2(zl, zh);
        }
        {
            int k = 2 * p + 1;
            float2 g = Gb[k * NN + t];
            float zl = fmaxf(cb + u_sh[k] + g.x, 0.f);
            float zh = fmaxf(cb + v_sh[k] + g.y, 0.f);
            zp[k] = pack2(zl, zh);
        }
    }

    // ---- layer2 (32x32) + relu + layer3, both directions in f32x2 ----
    float oij = 0.f, oji = 0.f;
    #pragma unroll
    for (int tile = 0; tile < 4; tile++) {
        u64 acc[8];
        #pragma unroll
        for (int o = 0; o < 8; o++) acc[o] = b2d[tile * 8 + o];
        #pragma unroll
        for (int ki = 0; ki < 32; ki++) {
            u64 z = zp[ki];
            #pragma unroll
            for (int o = 0; o < 8; o++)
                acc[o] = fma2(z, w2d[ki][tile * 8 + o], acc[o]);
        }
        #pragma unroll
        for (int o = 0; o < 8; o++) {
            float alo, ahi;
            unpack2(acc[o], alo, ahi);
            float w3v = w3_sh[tile * 8 + o];
            oij = fmaf(fmaxf(alo, 0.f), w3v, oij);
            oji = fmaf(fmaxf(ahi, 0.f), w3v, oji);
        }
    }

    // ---- antisymmetrize + block reduce over j ----
    float r = (oij - oji) * mask[(size_t)bi * NN + t];
    #pragma unroll
    for (int off = 16; off > 0; off >>= 1)
        r += __shfl_down_sync(0xffffffffu, r, off);
    if ((t & 31) == 0) red[t >> 5] = r;
    __syncthreads();
    if (t == 0) out[bi] = q[bi] + red[0] + red[1] + red[2];
}

extern "C" void kernel_launch(void* const* d_in, const int* in_sizes, int n_in,
                              void* d_out, int out_size) {
    const float* h    = (const float*)d_in[0];
    const float* e    = (const float*)d_in[1];
    const float* q    = (const float*)d_in[2];
    const float* mask = (const float*)d_in[3];
    const float* W1   = (const float*)d_in[4];
    const float* b1   = (const float*)d_in[5];
    const float* W2   = (const float*)d_in[6];
    const float* b2   = (const float*)d_in[7];
    const float* W3   = (const float*)d_in[8];
    // d_in[9] = b3 cancels in the antisymmetric difference
    float* out = (float*)d_out;

    epn_prep_kernel<<<NNODE, 64>>>(h, q, W1);
    epn_main_kernel<<<NNODE, 96>>>(e, q, mask, W1, b1, W2, b2, W3, out);
}